// round 9
// baseline (speedup 1.0000x reference)
#include <cuda_runtime.h>

// Fused HybridSamplerConv, round 8: ONE graph node, 8 samples/thread.
// R7 analysis: 32 warps x 6 LDG.128 = 24.5 KB in flight/SM, exactly at the
// Little's-law requirement (42.6 B/cyc/SM x 577 cyc = 24.6 KB) -> no slack,
// DRAM stuck at 63%. Occupancy is reg-tier-locked, so raise per-warp MLP:
// 12 front-batched LDG.128/thread -> 36.9 KB in flight at 24 warps/SM.

__device__ __forceinline__ float tanh_fast(float x) {
    float y;
    asm("tanh.approx.f32 %0, %1;" : "=f"(y) : "f"(x));
    return y;
}

__global__ void __launch_bounds__(256)
hybrid_sampler_kernel(const float4* __restrict__ inp,    // [B/2]: 2 samples per float4
                      const float4* __restrict__ data,   // [B]:   1 sample per float4
                      const float4* __restrict__ conv_w, // 4 floats
                      const float*  __restrict__ conv_b, // 1 float
                      const float4* __restrict__ w1v,    // 12 floats = 3 x float4
                      const float4* __restrict__ b1v,    // 4 floats
                      const float4* __restrict__ w2v,    // 8 floats = 2 x float4
                      const float2* __restrict__ b2v,    // 2 floats
                      float4*       __restrict__ out,    // [B/2]
                      int nocts)                         // B/8
{
    int i = blockIdx.x * blockDim.x + threadIdx.x;
    if (i >= nocts) return;

    // --- streaming loads: 12x 128-bit, front-batched (MLP_p1 = 12) ---
    float4 in01 = inp[4 * i + 0];
    float4 in23 = inp[4 * i + 1];
    float4 in45 = inp[4 * i + 2];
    float4 in67 = inp[4 * i + 3];
    float4 dd[8];
#pragma unroll
    for (int k = 0; k < 8; ++k) dd[k] = data[8 * i + k];

    // --- uniform parameter loads (L1-broadcast) ---
    float4 cw   = __ldg(conv_w);
    float  cb   = __ldg(conv_b);
    float4 w1r0 = __ldg(w1v + 0);
    float4 w1r1 = __ldg(w1v + 1);
    float4 w1r2 = __ldg(w1v + 2);
    float4 b1   = __ldg(b1v);
    float4 w2a  = __ldg(w2v + 0);   // (w2[0][0], w2[0][1], w2[1][0], w2[1][1])
    float4 w2b  = __ldg(w2v + 1);   // (w2[2][0], w2[2][1], w2[3][0], w2[3][1])
    float2 b2   = __ldg(b2v);

    // Fold output layer to logit-difference weights (w2/b2 die here).
    float g0 = w2a.y - w2a.x;
    float g1 = w2a.w - w2a.z;
    float g2 = w2b.y - w2b.x;
    float g3 = w2b.w - w2b.z;
    float gb = b2.y  - b2.x;

    float4 res[4];

#pragma unroll
    for (int s = 0; s < 8; ++s) {
        float in0, in1;
        switch (s) {
            case 0: in0 = in01.x; in1 = in01.y; break;
            case 1: in0 = in01.z; in1 = in01.w; break;
            case 2: in0 = in23.x; in1 = in23.y; break;
            case 3: in0 = in23.z; in1 = in23.w; break;
            case 4: in0 = in45.x; in1 = in45.y; break;
            case 5: in0 = in45.z; in1 = in45.w; break;
            case 6: in0 = in67.x; in1 = in67.y; break;
            default: in0 = in67.z; in1 = in67.w; break;
        }
        float4 d = dd[s];

        // conv 2x2 -> sigmoid via tanh identity (THRESHOLD = 0)
        float logit = fmaf(d.x, cw.x, fmaf(d.y, cw.y,
                      fmaf(d.z, cw.z, fmaf(d.w, cw.w, cb))));
        float conv = fmaf(tanh_fast(0.5f * logit), 0.5f, 0.5f);

        // h = tanh([in0, in1, conv] @ w1 + b1)
        float h0 = tanh_fast(fmaf(in0, w1r0.x, fmaf(in1, w1r1.x, fmaf(conv, w1r2.x, b1.x))));
        float h1 = tanh_fast(fmaf(in0, w1r0.y, fmaf(in1, w1r1.y, fmaf(conv, w1r2.y, b1.y))));
        float h2 = tanh_fast(fmaf(in0, w1r0.z, fmaf(in1, w1r1.z, fmaf(conv, w1r2.z, b1.z))));
        float h3 = tanh_fast(fmaf(in0, w1r0.w, fmaf(in1, w1r1.w, fmaf(conv, w1r2.w, b1.w))));

        // dz = z1 - z0, then softmax-of-2 from the difference (exact)
        float dz = fmaf(h0, g0, fmaf(h1, g1, fmaf(h2, g2, fmaf(h3, g3, gb))));
        float e = __expf(dz);
        float r = 1.0f / (1.0f + e);

        if (s & 1) { res[s >> 1].z = r; res[s >> 1].w = e * r; }
        else       { res[s >> 1].x = r; res[s >> 1].y = e * r; }
    }

#pragma unroll
    for (int k = 0; k < 4; ++k) out[4 * i + k] = res[k];
}

extern "C" void kernel_launch(void* const* d_in, const int* in_sizes, int n_in,
                              void* d_out, int out_size)
{
    const float* inp    = (const float*)d_in[0]; // [B,2]
    const float* data   = (const float*)d_in[1]; // [B,2,2]
    const float* conv_w = (const float*)d_in[2];
    const float* conv_b = (const float*)d_in[3];
    const float* w1     = (const float*)d_in[4];
    const float* b1     = (const float*)d_in[5];
    const float* w2     = (const float*)d_in[6];
    const float* b2     = (const float*)d_in[7];
    float* out          = (float*)d_out;

    int B = in_sizes[0] / 2;   // samples
    int nocts = B / 8;         // 8 samples per thread (B = 4M, divisible)

    int threads = 256;
    int blocks = (nocts + threads - 1) / threads;

    hybrid_sampler_kernel<<<blocks, threads>>>(
        (const float4*)inp, (const float4*)data,
        (const float4*)conv_w, conv_b,
        (const float4*)w1, (const float4*)b1,
        (const float4*)w2, (const float2*)b2,
        (float4*)out, nocts);
}

// round 10
// speedup vs baseline: 1.0785x; 1.0785x over previous
#include <cuda_runtime.h>

// Fused HybridSamplerConv, round 9: 8 samples/thread WITH the register budget
// to hold them. R8 failed because ptxas's default heuristic capped regs at 64
// and spilled the 12-load working set to local (L1 75%, DRAM 43%).
// __launch_bounds__(256, 3) raises the ceiling to 85 regs -> 24 warps/SM,
// 24 x 12 x 128B = 36.9 KB in flight (vs 24.6 KB Little's-law requirement).
// All streaming values in explicit named registers (no arrays -> no local).

__device__ __forceinline__ float tanh_fast(float x) {
    float y;
    asm("tanh.approx.f32 %0, %1;" : "=f"(y) : "f"(x));
    return y;
}

__global__ void __launch_bounds__(256, 3)
hybrid_sampler_kernel(const float4* __restrict__ inp,    // [B/2]: 2 samples per float4
                      const float4* __restrict__ data,   // [B]:   1 sample per float4
                      const float4* __restrict__ conv_w,
                      const float*  __restrict__ conv_b,
                      const float4* __restrict__ w1v,    // 3 x float4
                      const float4* __restrict__ b1v,
                      const float4* __restrict__ w2v,    // 2 x float4
                      const float2* __restrict__ b2v,
                      float4*       __restrict__ out,    // [B/2]
                      int nocts)                         // B/8
{
    int i = blockIdx.x * blockDim.x + threadIdx.x;
    if (i >= nocts) return;

    // --- streaming loads: 12x 128-bit, front-batched (MLP_p1 = 12) ---
    float4 in01 = inp[4 * i + 0];
    float4 in23 = inp[4 * i + 1];
    float4 in45 = inp[4 * i + 2];
    float4 in67 = inp[4 * i + 3];
    float4 d0 = data[8 * i + 0];
    float4 d1 = data[8 * i + 1];
    float4 d2 = data[8 * i + 2];
    float4 d3 = data[8 * i + 3];
    float4 d4 = data[8 * i + 4];
    float4 d5 = data[8 * i + 5];
    float4 d6 = data[8 * i + 6];
    float4 d7 = data[8 * i + 7];

    // --- uniform parameter loads (L1-broadcast) ---
    float4 cw   = __ldg(conv_w);
    float  cb   = __ldg(conv_b);
    float4 w1r0 = __ldg(w1v + 0);
    float4 w1r1 = __ldg(w1v + 1);
    float4 w1r2 = __ldg(w1v + 2);
    float4 b1   = __ldg(b1v);
    float4 w2a  = __ldg(w2v + 0);   // (w2[0][0], w2[0][1], w2[1][0], w2[1][1])
    float4 w2b  = __ldg(w2v + 1);   // (w2[2][0], w2[2][1], w2[3][0], w2[3][1])
    float2 b2   = __ldg(b2v);

    // Fold output layer to logit-difference weights (w2/b2 die here).
    float g0 = w2a.y - w2a.x;
    float g1 = w2a.w - w2a.z;
    float g2 = w2b.y - w2b.x;
    float g3 = w2b.w - w2b.z;
    float gb = b2.y  - b2.x;

    // Per-sample pipeline as a lambda over explicit values (no arrays).
    auto run = [&](float in0, float in1, const float4& d) -> float2 {
        float logit = fmaf(d.x, cw.x, fmaf(d.y, cw.y,
                      fmaf(d.z, cw.z, fmaf(d.w, cw.w, cb))));
        float conv = fmaf(tanh_fast(0.5f * logit), 0.5f, 0.5f);

        float h0 = tanh_fast(fmaf(in0, w1r0.x, fmaf(in1, w1r1.x, fmaf(conv, w1r2.x, b1.x))));
        float h1 = tanh_fast(fmaf(in0, w1r0.y, fmaf(in1, w1r1.y, fmaf(conv, w1r2.y, b1.y))));
        float h2 = tanh_fast(fmaf(in0, w1r0.z, fmaf(in1, w1r1.z, fmaf(conv, w1r2.z, b1.z))));
        float h3 = tanh_fast(fmaf(in0, w1r0.w, fmaf(in1, w1r1.w, fmaf(conv, w1r2.w, b1.w))));

        float dz = fmaf(h0, g0, fmaf(h1, g1, fmaf(h2, g2, fmaf(h3, g3, gb))));
        float e = __expf(dz);
        float r = 1.0f / (1.0f + e);
        return make_float2(r, e * r);
    };

    float2 o0 = run(in01.x, in01.y, d0);
    float2 o1 = run(in01.z, in01.w, d1);
    float2 o2 = run(in23.x, in23.y, d2);
    float2 o3 = run(in23.z, in23.w, d3);
    float2 o4 = run(in45.x, in45.y, d4);
    float2 o5 = run(in45.z, in45.w, d5);
    float2 o6 = run(in67.x, in67.y, d6);
    float2 o7 = run(in67.z, in67.w, d7);

    out[4 * i + 0] = make_float4(o0.x, o0.y, o1.x, o1.y);
    out[4 * i + 1] = make_float4(o2.x, o2.y, o3.x, o3.y);
    out[4 * i + 2] = make_float4(o4.x, o4.y, o5.x, o5.y);
    out[4 * i + 3] = make_float4(o6.x, o6.y, o7.x, o7.y);
}

extern "C" void kernel_launch(void* const* d_in, const int* in_sizes, int n_in,
                              void* d_out, int out_size)
{
    const float* inp    = (const float*)d_in[0]; // [B,2]
    const float* data   = (const float*)d_in[1]; // [B,2,2]
    const float* conv_w = (const float*)d_in[2];
    const float* conv_b = (const float*)d_in[3];
    const float* w1     = (const float*)d_in[4];
    const float* b1     = (const float*)d_in[5];
    const float* w2     = (const float*)d_in[6];
    const float* b2     = (const float*)d_in[7];
    float* out          = (float*)d_out;

    int B = in_sizes[0] / 2;   // samples
    int nocts = B / 8;         // 8 samples per thread (B = 2^22, divisible)

    int threads = 256;
    int blocks = (nocts + threads - 1) / threads;

    hybrid_sampler_kernel<<<blocks, threads>>>(
        (const float4*)inp, (const float4*)data,
        (const float4*)conv_w, conv_b,
        (const float4*)w1, (const float4*)b1,
        (const float4*)w2, (const float2*)b2,
        (float4*)out, nocts);
}

// round 11
// speedup vs baseline: 1.2675x; 1.1752x over previous
#include <cuda_runtime.h>

// Fused HybridSamplerConv, round 10: persistent grid-stride kernel.
// Lessons: 6 LDG.128 front-batch @ 32 warps/SM is the measured sweet spot
// (R7: 22.4us); 12-wide batches overflow the L1tex wavefront queue (R8/R9).
// This round keeps the R7 body but makes the kernel persistent:
//  - params loaded ONCE per thread (amortized over ~7 iterations)
//  - #pragma unroll 2 lets ptxas overlap next iteration's loads with the
//    current iteration's tanh/exp tail
//  - grid = 152 SMs x 4 blocks, one graph node.

__device__ __forceinline__ float tanh_fast(float x) {
    float y;
    asm("tanh.approx.f32 %0, %1;" : "=f"(y) : "f"(x));
    return y;
}

__global__ void __launch_bounds__(256)
hybrid_sampler_kernel(const float4* __restrict__ inp,    // [B/2]
                      const float4* __restrict__ data,   // [B]
                      const float4* __restrict__ conv_w,
                      const float*  __restrict__ conv_b,
                      const float4* __restrict__ w1v,    // 3 x float4
                      const float4* __restrict__ b1v,
                      const float4* __restrict__ w2v,    // 2 x float4
                      const float2* __restrict__ b2v,
                      float4*       __restrict__ out,    // [B/2]
                      int nquads)                        // B/4
{
    // --- uniform parameter loads: once per thread, L1-broadcast ---
    float4 cw   = __ldg(conv_w);
    float  cb   = __ldg(conv_b);
    float4 w1r0 = __ldg(w1v + 0);
    float4 w1r1 = __ldg(w1v + 1);
    float4 w1r2 = __ldg(w1v + 2);
    float4 b1   = __ldg(b1v);
    float4 w2a  = __ldg(w2v + 0);   // (w2[0][0], w2[0][1], w2[1][0], w2[1][1])
    float4 w2b  = __ldg(w2v + 1);   // (w2[2][0], w2[2][1], w2[3][0], w2[3][1])
    float2 b2   = __ldg(b2v);

    // Fold output layer to logit-difference weights (w2/b2 die here).
    float g0 = w2a.y - w2a.x;
    float g1 = w2a.w - w2a.z;
    float g2 = w2b.y - w2b.x;
    float g3 = w2b.w - w2b.z;
    float gb = b2.y  - b2.x;

    int stride = gridDim.x * blockDim.x;

#pragma unroll 2
    for (int i = blockIdx.x * blockDim.x + threadIdx.x; i < nquads; i += stride) {
        // 6x 128-bit streaming loads, front-batched (MLP_p1 = 6)
        float4 inA = inp[2 * i + 0];
        float4 inB = inp[2 * i + 1];
        float4 d0  = data[4 * i + 0];
        float4 d1  = data[4 * i + 1];
        float4 d2  = data[4 * i + 2];
        float4 d3  = data[4 * i + 3];

        float4 resA, resB;

#pragma unroll
        for (int s = 0; s < 4; ++s) {
            float in0, in1;
            float4 d;
            if      (s == 0) { in0 = inA.x; in1 = inA.y; d = d0; }
            else if (s == 1) { in0 = inA.z; in1 = inA.w; d = d1; }
            else if (s == 2) { in0 = inB.x; in1 = inB.y; d = d2; }
            else             { in0 = inB.z; in1 = inB.w; d = d3; }

            // conv 2x2 -> sigmoid via tanh identity (THRESHOLD = 0)
            float logit = fmaf(d.x, cw.x, fmaf(d.y, cw.y,
                          fmaf(d.z, cw.z, fmaf(d.w, cw.w, cb))));
            float conv = fmaf(tanh_fast(0.5f * logit), 0.5f, 0.5f);

            // h = tanh([in0, in1, conv] @ w1 + b1)
            float h0 = tanh_fast(fmaf(in0, w1r0.x, fmaf(in1, w1r1.x, fmaf(conv, w1r2.x, b1.x))));
            float h1 = tanh_fast(fmaf(in0, w1r0.y, fmaf(in1, w1r1.y, fmaf(conv, w1r2.y, b1.y))));
            float h2 = tanh_fast(fmaf(in0, w1r0.z, fmaf(in1, w1r1.z, fmaf(conv, w1r2.z, b1.z))));
            float h3 = tanh_fast(fmaf(in0, w1r0.w, fmaf(in1, w1r1.w, fmaf(conv, w1r2.w, b1.w))));

            // dz = z1 - z0, then exact softmax-of-2 from the difference
            float dz = fmaf(h0, g0, fmaf(h1, g1, fmaf(h2, g2, fmaf(h3, g3, gb))));
            float e = __expf(dz);
            float r = 1.0f / (1.0f + e);
            float o0 = r, o1 = e * r;

            if      (s == 0) { resA.x = o0; resA.y = o1; }
            else if (s == 1) { resA.z = o0; resA.w = o1; }
            else if (s == 2) { resB.x = o0; resB.y = o1; }
            else             { resB.z = o0; resB.w = o1; }
        }

        out[2 * i + 0] = resA;
        out[2 * i + 1] = resB;
    }
}

extern "C" void kernel_launch(void* const* d_in, const int* in_sizes, int n_in,
                              void* d_out, int out_size)
{
    const float* inp    = (const float*)d_in[0]; // [B,2]
    const float* data   = (const float*)d_in[1]; // [B,2,2]
    const float* conv_w = (const float*)d_in[2];
    const float* conv_b = (const float*)d_in[3];
    const float* w1     = (const float*)d_in[4];
    const float* b1     = (const float*)d_in[5];
    const float* w2     = (const float*)d_in[6];
    const float* b2     = (const float*)d_in[7];
    float* out          = (float*)d_out;

    int B = in_sizes[0] / 2;   // samples
    int nquads = B / 4;        // 4 samples per iteration per thread

    // Persistent grid: 152 SMs (GB300) x 4 blocks of 256 threads.
    int threads = 256;
    int blocks = 152 * 4;

    hybrid_sampler_kernel<<<blocks, threads>>>(
        (const float4*)inp, (const float4*)data,
        (const float4*)conv_w, conv_b,
        (const float4*)w1, (const float4*)b1,
        (const float4*)w2, (const float2*)b2,
        (float4*)out, nquads);
}